// round 2
// baseline (speedup 1.0000x reference)
#include <cuda_runtime.h>
#include <math.h>

#define T_DATA 20000
#define E_NO   2000
#define I_NO   500
#define M_NO   10
#define TN     200
#define B_NO   12
#define ITERS  10

// -------- device scratch (static, no allocation) --------
__device__ float g_u[T_DATA];
__device__ float g_v[T_DATA];
__device__ float g_re[M_NO * TN];   // re[m][d] = ke[m][199-d]  (delay-d conv coeff, d=0..199)
__device__ float g_ri[M_NO * TN];
__device__ float g_K [M_NO * TN];   // K[m][j]  = feedback coeff for delay d=j+1 (ll folded into j=0)
__device__ float g_ml[M_NO];
__device__ float g_b0;
__device__ float g_sconv[M_NO * T_DATA];  // plane-major: [m][t]
__device__ float g_outA[T_DATA];
__device__ float g_outB[T_DATA];

// -------- K0: tiny weight products (1 block) --------
__global__ void k0_small(const float* __restrict__ be, const float* __restrict__ we,
                         const float* __restrict__ bi, const float* __restrict__ wi,
                         const float* __restrict__ bh, const float* __restrict__ wh,
                         const float* __restrict__ ll, const float* __restrict__ ml,
                         const float* __restrict__ mb)
{
    int tid = threadIdx.x;
    for (int i = tid; i < M_NO * TN; i += blockDim.x) {
        int m = i / TN, k = i % TN;
        float se = 0.f, si = 0.f, sh = 0.f;
        #pragma unroll
        for (int b = 0; b < B_NO; b++) {
            se = fmaf(we[m * B_NO + b], be[b * TN + k], se);
            si = fmaf(wi[m * B_NO + b], bi[b * TN + k], si);
            sh = fmaf(wh[m * B_NO + b], bh[b * TN + k], sh);
        }
        // ke[m][k] is the coeff for delay d = 199-k  -> re[m][199-k]
        g_re[m * TN + (TN - 1 - k)] = se;
        g_ri[m * TN + (TN - 1 - k)] = si;
        // hk[m][k] is the coeff for delay d = 200-k -> K index j = d-1 = 199-k
        float kk = sh;
        if (k == TN - 1) kk += ll[m];     // delay d=1 also carries leaf_linear
        g_K[m * TN + (TN - 1 - k)] = kk;
    }
    if (tid < M_NO) g_ml[tid] = ml[tid];   // multiplex_linear row 0
    if (tid == 0)   g_b0 = mb[0];
}

// -------- K1: u[t] = S_e[t,:] . C_syn_e[0,:] ; v[t] = S_i[t,:] . C_syn_i[0,:] --------
// one warp per row, float4 loads; HBM-bound (200 MB)
__global__ __launch_bounds__(256) void k1_proj(const float* __restrict__ Se,
                                               const float* __restrict__ Si,
                                               const float* __restrict__ Ce,
                                               const float* __restrict__ Ci)
{
    int gw   = (blockIdx.x * blockDim.x + threadIdx.x) >> 5;
    int lane = threadIdx.x & 31;
    if (gw < T_DATA) {
        const float4* row = reinterpret_cast<const float4*>(Se) + (size_t)gw * (E_NO / 4);
        const float4* w   = reinterpret_cast<const float4*>(Ce);
        float acc = 0.f;
        #pragma unroll 4
        for (int i = lane; i < E_NO / 4; i += 32) {
            float4 a = row[i];
            float4 b = __ldg(w + i);
            acc = fmaf(a.x, b.x, fmaf(a.y, b.y, fmaf(a.z, b.z, fmaf(a.w, b.w, acc))));
        }
        #pragma unroll
        for (int o = 16; o; o >>= 1) acc += __shfl_down_sync(0xffffffffu, acc, o);
        if (!lane) g_u[gw] = acc;
    } else {
        int t = gw - T_DATA;
        const float4* row = reinterpret_cast<const float4*>(Si) + (size_t)t * (I_NO / 4);
        const float4* w   = reinterpret_cast<const float4*>(Ci);
        float acc = 0.f;
        #pragma unroll
        for (int i = lane; i < I_NO / 4; i += 32) {
            float4 a = row[i];
            float4 b = __ldg(w + i);
            acc = fmaf(a.x, b.x, fmaf(a.y, b.y, fmaf(a.z, b.z, fmaf(a.w, b.w, acc))));
        }
        #pragma unroll
        for (int o = 16; o; o >>= 1) acc += __shfl_down_sync(0xffffffffu, acc, o);
        if (!lane) g_v[t] = acc;
    }
}

// -------- K2: sconv[m][t] = sum_d re[m][d]*u[t-d] + ri[m][d]*v[t-d] --------
#define TILE2 128
__global__ __launch_bounds__(320) void k2_sconv()
{
    __shared__ float su[TILE2 + TN];
    __shared__ float sv[TILE2 + TN];
    __shared__ float sre[M_NO * TN];
    __shared__ float sri[M_NO * TN];

    int t0  = blockIdx.x * TILE2;
    int tid = threadIdx.x;

    for (int i = tid; i < M_NO * TN; i += 320) { sre[i] = g_re[i]; sri[i] = g_ri[i]; }
    for (int i = tid; i < TILE2 + TN - 1; i += 320) {
        int t = t0 - (TN - 1) + i;
        bool ok = (t >= 0 && t < T_DATA);
        su[i] = ok ? g_u[t] : 0.f;
        sv[i] = ok ? g_v[t] : 0.f;
    }
    __syncthreads();

    int m = tid >> 5, tt = tid & 31;
    const float* re = &sre[m * TN];
    const float* ri = &sri[m * TN];
    float a0 = 0.f, a1 = 0.f, a2 = 0.f, a3 = 0.f;
    #pragma unroll 4
    for (int d = 0; d < TN; d++) {
        float ce = re[d], ci = ri[d];
        int base = tt + (TN - 1) - d;
        a0 = fmaf(ce, su[base      ], a0); a0 = fmaf(ci, sv[base      ], a0);
        a1 = fmaf(ce, su[base +  32], a1); a1 = fmaf(ci, sv[base +  32], a1);
        a2 = fmaf(ce, su[base +  64], a2); a2 = fmaf(ci, sv[base +  64], a2);
        a3 = fmaf(ce, su[base +  96], a3); a3 = fmaf(ci, sv[base +  96], a3);
    }
    float acc[4] = {a0, a1, a2, a3};
    #pragma unroll
    for (int j = 0; j < 4; j++) {
        int t = t0 + tt + 32 * j;
        if (t < T_DATA) g_sconv[m * T_DATA + t] = acc[j];
    }
}

// -------- K3: one Jacobi sweep of the nonlinear AR(200) --------
// out_new[t] = b + sum_m ml[m]*tanh(sconv[m][t] + sum_j K[m][j]*out_old[t-1-j])
#define TILE3 128
__global__ __launch_bounds__(320) void k3_iter(float* __restrict__ final_out,
                                               int first, int src_sel, int dst_sel)
{
    __shared__ float so[TILE3 + TN];       // out_old window [t0-200, t0+127]
    __shared__ float sK[M_NO * TN];
    __shared__ float p[TILE3 * 11];        // pitch 11: conflict-free partials

    const float* src = src_sel ? g_outB : g_outA;
    float* dst = (dst_sel == 2) ? final_out : (dst_sel ? g_outB : g_outA);

    int t0  = blockIdx.x * TILE3;
    int tid = threadIdx.x;

    for (int i = tid; i < M_NO * TN; i += 320) sK[i] = g_K[i];
    for (int i = tid; i < TILE3 + TN; i += 320) {
        int t = t0 - TN + i;
        so[i] = (!first && t >= 0 && t < T_DATA) ? src[t] : 0.f;
    }
    __syncthreads();

    int m = tid >> 5, tt = tid & 31;
    const float* K = &sK[m * TN];
    float f0 = 0.f, f1 = 0.f, f2 = 0.f, f3 = 0.f;
    #pragma unroll 4
    for (int j = 0; j < TN; j++) {
        float c = K[j];
        int base = tt + (TN - 1) - j;      // so index for out_old[t-1-j], t = t0+tt
        f0 = fmaf(c, so[base      ], f0);
        f1 = fmaf(c, so[base +  32], f1);
        f2 = fmaf(c, so[base +  64], f2);
        f3 = fmaf(c, so[base +  96], f3);
    }
    float fb[4] = {f0, f1, f2, f3};
    float mlm = g_ml[m];
    #pragma unroll
    for (int j = 0; j < 4; j++) {
        int t  = t0 + tt + 32 * j;
        int tl = tt + 32 * j;
        float sc  = (t < T_DATA) ? g_sconv[m * T_DATA + t] : 0.f;
        p[tl * 11 + m] = mlm * tanhf(sc + fb[j]);
    }
    __syncthreads();

    if (tid < TILE3) {
        int t = t0 + tid;
        if (t < T_DATA) {
            float s = g_b0;
            #pragma unroll
            for (int m2 = 0; m2 < M_NO; m2++) s += p[tid * 11 + m2];
            dst[t] = s;
        }
    }
}

// -------- launch --------
extern "C" void kernel_launch(void* const* d_in, const int* in_sizes, int n_in,
                              void* d_out, int out_size)
{
    const float* S_e  = (const float*)d_in[0];
    const float* S_i  = (const float*)d_in[1];
    // d_in[2] = C_den (unused)
    const float* Ce   = (const float*)d_in[3];
    const float* Ci   = (const float*)d_in[4];
    const float* be   = (const float*)d_in[5];
    const float* we   = (const float*)d_in[6];
    const float* bi   = (const float*)d_in[7];
    const float* wi   = (const float*)d_in[8];
    const float* bh   = (const float*)d_in[9];
    const float* wh   = (const float*)d_in[10];
    const float* ll   = (const float*)d_in[11];
    const float* ml   = (const float*)d_in[12];
    const float* mb   = (const float*)d_in[13];
    float* out = (float*)d_out;

    k0_small<<<1, 256>>>(be, we, bi, wi, bh, wh, ll, ml, mb);
    k1_proj<<<(2 * T_DATA * 32) / 256, 256>>>(S_e, S_i, Ce, Ci);

    int grid = (T_DATA + TILE2 - 1) / TILE2;   // 157
    k2_sconv<<<grid, 320>>>();

    // Jacobi sweeps: iter 0 uses exact zero history (deterministic across replays)
    k3_iter<<<grid, 320>>>(out, 1, 0, 0);                     // -> A
    for (int i = 1; i < ITERS; i++) {
        int src = (i + 1) & 1;                                 // i=1 reads A
        int dst = i & 1;
        k3_iter<<<grid, 320>>>(out, 0, src, (i == ITERS - 1) ? 2 : dst);
    }
}

// round 4
// speedup vs baseline: 1.7366x; 1.7366x over previous
#include <cuda_runtime.h>
#include <math.h>

#define T_DATA 20000
#define E_NO   2000
#define I_NO   500
#define M_NO   10
#define TN     200
#define B_NO   12

// -------- device scratch (static, no allocation) --------
__device__ float g_u[T_DATA];
__device__ float g_v[T_DATA];
__device__ float g_re[M_NO * TN];   // re[m][d] = ke[m][199-d]  (delay-d conv coeff, d=0..199)
__device__ float g_ri[M_NO * TN];
__device__ float g_K [M_NO * TN];   // K[m][j]  = feedback coeff for delay d=j+1 (ll folded into j=0)
__device__ float g_ml[M_NO];
__device__ float g_b0;
__device__ float g_sconv[M_NO * T_DATA];  // plane-major: [m][t]
__device__ float g_outA[T_DATA];
__device__ float g_outB[T_DATA];

// -------- K0: tiny weight products (1 block) --------
__global__ void k0_small(const float* __restrict__ be, const float* __restrict__ we,
                         const float* __restrict__ bi, const float* __restrict__ wi,
                         const float* __restrict__ bh, const float* __restrict__ wh,
                         const float* __restrict__ ll, const float* __restrict__ ml,
                         const float* __restrict__ mb)
{
    int tid = threadIdx.x;
    for (int i = tid; i < M_NO * TN; i += blockDim.x) {
        int m = i / TN, k = i % TN;
        float se = 0.f, si = 0.f, sh = 0.f;
        #pragma unroll
        for (int b = 0; b < B_NO; b++) {
            se = fmaf(we[m * B_NO + b], be[b * TN + k], se);
            si = fmaf(wi[m * B_NO + b], bi[b * TN + k], si);
            sh = fmaf(wh[m * B_NO + b], bh[b * TN + k], sh);
        }
        g_re[m * TN + (TN - 1 - k)] = se;
        g_ri[m * TN + (TN - 1 - k)] = si;
        float kk = sh;
        if (k == TN - 1) kk += ll[m];     // delay d=1 also carries leaf_linear
        g_K[m * TN + (TN - 1 - k)] = kk;
    }
    if (tid < M_NO) g_ml[tid] = ml[tid];
    if (tid == 0)   g_b0 = mb[0];
}

// -------- K1: u[t] = S_e[t,:].Ce[0,:] ; v[t] = S_i[t,:].Ci[0,:]  (HBM-bound, 200 MB) --------
__global__ __launch_bounds__(256) void k1_proj(const float* __restrict__ Se,
                                               const float* __restrict__ Si,
                                               const float* __restrict__ Ce,
                                               const float* __restrict__ Ci)
{
    int gw   = (blockIdx.x * blockDim.x + threadIdx.x) >> 5;
    int lane = threadIdx.x & 31;
    if (gw < T_DATA) {
        const float4* row = reinterpret_cast<const float4*>(Se) + (size_t)gw * (E_NO / 4);
        const float4* w   = reinterpret_cast<const float4*>(Ce);
        float acc = 0.f;
        #pragma unroll 4
        for (int i = lane; i < E_NO / 4; i += 32) {
            float4 a = row[i];
            float4 b = __ldg(w + i);
            acc = fmaf(a.x, b.x, fmaf(a.y, b.y, fmaf(a.z, b.z, fmaf(a.w, b.w, acc))));
        }
        #pragma unroll
        for (int o = 16; o; o >>= 1) acc += __shfl_down_sync(0xffffffffu, acc, o);
        if (!lane) g_u[gw] = acc;
    } else {
        int t = gw - T_DATA;
        const float4* row = reinterpret_cast<const float4*>(Si) + (size_t)t * (I_NO / 4);
        const float4* w   = reinterpret_cast<const float4*>(Ci);
        float acc = 0.f;
        #pragma unroll
        for (int i = lane; i < I_NO / 4; i += 32) {
            float4 a = row[i];
            float4 b = __ldg(w + i);
            acc = fmaf(a.x, b.x, fmaf(a.y, b.y, fmaf(a.z, b.z, fmaf(a.w, b.w, acc))));
        }
        #pragma unroll
        for (int o = 16; o; o >>= 1) acc += __shfl_down_sync(0xffffffffu, acc, o);
        if (!lane) g_v[t] = acc;
    }
}

// -------- K2: sconv + fused sweep-0 (zero history => out0 = b + sum ml*tanh(sconv)) --------
// 640 threads = 20 warps; warp w -> (m = w>>1, half = w&1); 2 accumulators per warp.
#define TILE 128
__global__ __launch_bounds__(640) void k2_fused()
{
    __shared__ __align__(16) float su[TILE + TN];
    __shared__ __align__(16) float sv[TILE + TN];
    __shared__ __align__(16) float sre[M_NO * TN];
    __shared__ __align__(16) float sri[M_NO * TN];
    __shared__ float p[TILE * 11];

    int t0  = blockIdx.x * TILE;
    int tid = threadIdx.x;

    for (int i = tid; i < M_NO * TN; i += 640) { sre[i] = g_re[i]; sri[i] = g_ri[i]; }
    for (int i = tid; i < TILE + TN - 1; i += 640) {
        int t = t0 - (TN - 1) + i;
        bool ok = (t >= 0 && t < T_DATA);
        su[i] = ok ? g_u[t] : 0.f;
        sv[i] = ok ? g_v[t] : 0.f;
    }
    __syncthreads();

    int w = tid >> 5, tt = tid & 31;
    int m = w >> 1, half = w & 1;
    const float4* re4 = reinterpret_cast<const float4*>(&sre[m * TN]);
    const float4* ri4 = reinterpret_cast<const float4*>(&sri[m * TN]);
    float a0 = 0.f, a1 = 0.f;
    int base0 = half * 64 + tt + (TN - 1);   // su index for u[t-d] at d=0, t = t0+half*64+tt
    #pragma unroll 5
    for (int d = 0; d < TN; d += 4) {
        float4 ce = re4[d >> 2];
        float4 ci = ri4[d >> 2];
        int b = base0 - d;
        a0 = fmaf(ce.x, su[b    ], a0); a0 = fmaf(ci.x, sv[b    ], a0);
        a0 = fmaf(ce.y, su[b - 1], a0); a0 = fmaf(ci.y, sv[b - 1], a0);
        a0 = fmaf(ce.z, su[b - 2], a0); a0 = fmaf(ci.z, sv[b - 2], a0);
        a0 = fmaf(ce.w, su[b - 3], a0); a0 = fmaf(ci.w, sv[b - 3], a0);
        a1 = fmaf(ce.x, su[b + 32], a1); a1 = fmaf(ci.x, sv[b + 32], a1);
        a1 = fmaf(ce.y, su[b + 31], a1); a1 = fmaf(ci.y, sv[b + 31], a1);
        a1 = fmaf(ce.z, su[b + 30], a1); a1 = fmaf(ci.z, sv[b + 30], a1);
        a1 = fmaf(ce.w, su[b + 29], a1); a1 = fmaf(ci.w, sv[b + 29], a1);
    }

    float mlm = g_ml[m];
    float acc[2] = {a0, a1};
    #pragma unroll
    for (int j = 0; j < 2; j++) {
        int tl = half * 64 + tt + 32 * j;
        int t  = t0 + tl;
        if (t < T_DATA) g_sconv[m * T_DATA + t] = acc[j];
        p[tl * 11 + m] = mlm * tanhf(acc[j]);   // sweep-0: zero feedback
    }
    __syncthreads();

    if (tid < TILE) {
        int t = t0 + tid;
        if (t < T_DATA) {
            float s = g_b0;
            #pragma unroll
            for (int m2 = 0; m2 < M_NO; m2++) s += p[tid * 11 + m2];
            g_outA[t] = s;
        }
    }
}

// -------- K3: one Jacobi sweep --------
// out_new[t] = b + sum_m ml[m]*tanh(sconv[m][t] + sum_j K[m][j]*out_old[t-1-j])
__global__ __launch_bounds__(640) void k3_iter(float* __restrict__ final_out,
                                               int src_sel, int dst_sel)
{
    __shared__ __align__(16) float so[TILE + TN];    // out_old window [t0-200, t0+127]
    __shared__ __align__(16) float sK[M_NO * TN];
    __shared__ float p[TILE * 11];

    const float* src = src_sel ? g_outB : g_outA;
    float* dst = (dst_sel == 2) ? final_out : (dst_sel ? g_outB : g_outA);

    int t0  = blockIdx.x * TILE;
    int tid = threadIdx.x;

    for (int i = tid; i < M_NO * TN; i += 640) sK[i] = g_K[i];
    for (int i = tid; i < TILE + TN; i += 640) {
        int t = t0 - TN + i;
        so[i] = (t >= 0 && t < T_DATA) ? src[t] : 0.f;
    }
    __syncthreads();

    int w = tid >> 5, tt = tid & 31;
    int m = w >> 1, half = w & 1;
    const float4* K4 = reinterpret_cast<const float4*>(&sK[m * TN]);
    float f0 = 0.f, f1 = 0.f;
    int base0 = half * 64 + tt + (TN - 1);   // so index for out_old[t-1-j] at j=0
    #pragma unroll 5
    for (int j = 0; j < TN; j += 4) {
        float4 k4 = K4[j >> 2];
        int b = base0 - j;
        f0 = fmaf(k4.x, so[b    ], f0);
        f0 = fmaf(k4.y, so[b - 1], f0);
        f0 = fmaf(k4.z, so[b - 2], f0);
        f0 = fmaf(k4.w, so[b - 3], f0);
        f1 = fmaf(k4.x, so[b + 32], f1);
        f1 = fmaf(k4.y, so[b + 31], f1);
        f1 = fmaf(k4.z, so[b + 30], f1);
        f1 = fmaf(k4.w, so[b + 29], f1);
    }

    float mlm = g_ml[m];
    float fb[2] = {f0, f1};
    #pragma unroll
    for (int j = 0; j < 2; j++) {
        int tl = half * 64 + tt + 32 * j;
        int t  = t0 + tl;
        float sc = (t < T_DATA) ? g_sconv[m * T_DATA + t] : 0.f;
        p[tl * 11 + m] = mlm * tanhf(sc + fb[j]);
    }
    __syncthreads();

    if (tid < TILE) {
        int t = t0 + tid;
        if (t < T_DATA) {
            float s = g_b0;
            #pragma unroll
            for (int m2 = 0; m2 < M_NO; m2++) s += p[tid * 11 + m2];
            dst[t] = s;
        }
    }
}

// -------- launch --------
extern "C" void kernel_launch(void* const* d_in, const int* in_sizes, int n_in,
                              void* d_out, int out_size)
{
    const float* S_e  = (const float*)d_in[0];
    const float* S_i  = (const float*)d_in[1];
    // d_in[2] = C_den (unused)
    const float* Ce   = (const float*)d_in[3];
    const float* Ci   = (const float*)d_in[4];
    const float* be   = (const float*)d_in[5];
    const float* we   = (const float*)d_in[6];
    const float* bi   = (const float*)d_in[7];
    const float* wi   = (const float*)d_in[8];
    const float* bh   = (const float*)d_in[9];
    const float* wh   = (const float*)d_in[10];
    const float* ll   = (const float*)d_in[11];
    const float* ml   = (const float*)d_in[12];
    const float* mb   = (const float*)d_in[13];
    float* out = (float*)d_out;

    int grid = (T_DATA + TILE - 1) / TILE;   // 157

    k0_small<<<1, 256>>>(be, we, bi, wi, bh, wh, ll, ml, mb);
    k1_proj<<<(2 * T_DATA * 32) / 256, 256>>>(S_e, S_i, Ce, Ci);
    k2_fused<<<grid, 640>>>();               // sconv + sweep0 -> A

    k3_iter<<<grid, 640>>>(out, 0, 1);       // A -> B   (sweep 1)
    k3_iter<<<grid, 640>>>(out, 1, 0);       // B -> A   (sweep 2)
    k3_iter<<<grid, 640>>>(out, 0, 2);       // A -> out (sweep 3, final)
}

// round 6
// speedup vs baseline: 1.9819x; 1.1413x over previous
#include <cuda_runtime.h>
#include <math.h>

#define T_DATA 20000
#define E_NO   2000
#define I_NO   500
#define M_NO   10
#define TN     200
#define B_NO   12

// -------- device scratch (static, no allocation) --------
__device__ float g_u[T_DATA];
__device__ float g_v[T_DATA];
__device__ float g_re[M_NO * TN];   // re[m][d] = ke[m][199-d]
__device__ float g_ri[M_NO * TN];
__device__ float g_K [M_NO * TN];   // K[m][j] = feedback coeff, delay d=j+1 (ll folded into j=0)
__device__ float g_ml[M_NO];
__device__ float g_b0;
__device__ float g_sconv[M_NO * T_DATA];  // plane-major: [m][t]
__device__ float g_outA[T_DATA];
__device__ float g_outB[T_DATA];

// -------- K0: tiny weight products (1 block) --------
__global__ void k0_small(const float* __restrict__ be, const float* __restrict__ we,
                         const float* __restrict__ bi, const float* __restrict__ wi,
                         const float* __restrict__ bh, const float* __restrict__ wh,
                         const float* __restrict__ ll, const float* __restrict__ ml,
                         const float* __restrict__ mb)
{
    int tid = threadIdx.x;
    for (int i = tid; i < M_NO * TN; i += blockDim.x) {
        int m = i / TN, k = i % TN;
        float se = 0.f, si = 0.f, sh = 0.f;
        #pragma unroll
        for (int b = 0; b < B_NO; b++) {
            se = fmaf(we[m * B_NO + b], be[b * TN + k], se);
            si = fmaf(wi[m * B_NO + b], bi[b * TN + k], si);
            sh = fmaf(wh[m * B_NO + b], bh[b * TN + k], sh);
        }
        g_re[m * TN + (TN - 1 - k)] = se;
        g_ri[m * TN + (TN - 1 - k)] = si;
        float kk = sh;
        if (k == TN - 1) kk += ll[m];
        g_K[m * TN + (TN - 1 - k)] = kk;
    }
    if (tid < M_NO) g_ml[tid] = ml[tid];
    if (tid == 0)   g_b0 = mb[0];
}

// -------- K1: u[t] = S_e[t,:].Ce[0,:] ; v[t] = S_i[t,:].Ci[0,:]  (HBM-bound, 200 MB) --------
__global__ __launch_bounds__(256) void k1_proj(const float* __restrict__ Se,
                                               const float* __restrict__ Si,
                                               const float* __restrict__ Ce,
                                               const float* __restrict__ Ci)
{
    int gw   = (blockIdx.x * blockDim.x + threadIdx.x) >> 5;
    int lane = threadIdx.x & 31;
    if (gw < T_DATA) {
        const float4* row = reinterpret_cast<const float4*>(Se) + (size_t)gw * (E_NO / 4);
        const float4* w   = reinterpret_cast<const float4*>(Ce);
        float acc = 0.f;
        #pragma unroll 4
        for (int i = lane; i < E_NO / 4; i += 32) {
            float4 a = row[i];
            float4 b = __ldg(w + i);
            acc = fmaf(a.x, b.x, fmaf(a.y, b.y, fmaf(a.z, b.z, fmaf(a.w, b.w, acc))));
        }
        #pragma unroll
        for (int o = 16; o; o >>= 1) acc += __shfl_down_sync(0xffffffffu, acc, o);
        if (!lane) g_u[gw] = acc;
    } else {
        int t = gw - T_DATA;
        const float4* row = reinterpret_cast<const float4*>(Si) + (size_t)t * (I_NO / 4);
        const float4* w   = reinterpret_cast<const float4*>(Ci);
        float acc = 0.f;
        #pragma unroll
        for (int i = lane; i < I_NO / 4; i += 32) {
            float4 a = row[i];
            float4 b = __ldg(w + i);
            acc = fmaf(a.x, b.x, fmaf(a.y, b.y, fmaf(a.z, b.z, fmaf(a.w, b.w, acc))));
        }
        #pragma unroll
        for (int o = 16; o; o >>= 1) acc += __shfl_down_sync(0xffffffffu, acc, o);
        if (!lane) g_v[t] = acc;
    }
}

// -------- K2: sconv + fused sweep-0. 640 thr = 20 warps: warp w -> (m=w>>1, half=w&1).
// 8 independent FMA chains per warp: (tap-half a/b) x (e/i) x (t-group 0/1).
#define TILE 128
__global__ __launch_bounds__(640) void k2_fused()
{
    __shared__ __align__(16) float su[TILE + TN];
    __shared__ __align__(16) float sv[TILE + TN];
    __shared__ __align__(16) float sre[M_NO * TN];
    __shared__ __align__(16) float sri[M_NO * TN];
    __shared__ float p[TILE * 11];

    int t0  = blockIdx.x * TILE;
    int tid = threadIdx.x;

    for (int i = tid; i < M_NO * TN; i += 640) { sre[i] = g_re[i]; sri[i] = g_ri[i]; }
    for (int i = tid; i < TILE + TN - 1; i += 640) {
        int t = t0 - (TN - 1) + i;
        bool ok = (t >= 0 && t < T_DATA);
        su[i] = ok ? g_u[t] : 0.f;
        sv[i] = ok ? g_v[t] : 0.f;
    }
    __syncthreads();

    int w = tid >> 5, tt = tid & 31;
    int m = w >> 1, half = w & 1;
    const float4* re4 = reinterpret_cast<const float4*>(&sre[m * TN]);
    const float4* ri4 = reinterpret_cast<const float4*>(&sri[m * TN]);
    float e0a = 0.f, e1a = 0.f, i0a = 0.f, i1a = 0.f;
    float e0b = 0.f, e1b = 0.f, i0b = 0.f, i1b = 0.f;
    int base0 = half * 64 + tt + (TN - 1);
    #pragma unroll 2
    for (int d = 0; d < TN / 2; d += 4) {
        float4 cea = re4[d >> 2];
        float4 ceb = re4[(d + 100) >> 2];
        float4 cia = ri4[d >> 2];
        float4 cib = ri4[(d + 100) >> 2];
        int b  = base0 - d;
        int b2 = b - 100;
        e0a = fmaf(cea.x, su[b     ], e0a); e0a = fmaf(cea.y, su[b -  1], e0a);
        e0a = fmaf(cea.z, su[b -  2], e0a); e0a = fmaf(cea.w, su[b -  3], e0a);
        i0a = fmaf(cia.x, sv[b     ], i0a); i0a = fmaf(cia.y, sv[b -  1], i0a);
        i0a = fmaf(cia.z, sv[b -  2], i0a); i0a = fmaf(cia.w, sv[b -  3], i0a);
        e1a = fmaf(cea.x, su[b + 32], e1a); e1a = fmaf(cea.y, su[b + 31], e1a);
        e1a = fmaf(cea.z, su[b + 30], e1a); e1a = fmaf(cea.w, su[b + 29], e1a);
        i1a = fmaf(cia.x, sv[b + 32], i1a); i1a = fmaf(cia.y, sv[b + 31], i1a);
        i1a = fmaf(cia.z, sv[b + 30], i1a); i1a = fmaf(cia.w, sv[b + 29], i1a);
        e0b = fmaf(ceb.x, su[b2     ], e0b); e0b = fmaf(ceb.y, su[b2 -  1], e0b);
        e0b = fmaf(ceb.z, su[b2 -  2], e0b); e0b = fmaf(ceb.w, su[b2 -  3], e0b);
        i0b = fmaf(cib.x, sv[b2     ], i0b); i0b = fmaf(cib.y, sv[b2 -  1], i0b);
        i0b = fmaf(cib.z, sv[b2 -  2], i0b); i0b = fmaf(cib.w, sv[b2 -  3], i0b);
        e1b = fmaf(ceb.x, su[b2 + 32], e1b); e1b = fmaf(ceb.y, su[b2 + 31], e1b);
        e1b = fmaf(ceb.z, su[b2 + 30], e1b); e1b = fmaf(ceb.w, su[b2 + 29], e1b);
        i1b = fmaf(cib.x, sv[b2 + 32], i1b); i1b = fmaf(cib.y, sv[b2 + 31], i1b);
        i1b = fmaf(cib.z, sv[b2 + 30], i1b); i1b = fmaf(cib.w, sv[b2 + 29], i1b);
    }
    float acc[2];
    acc[0] = (e0a + e0b) + (i0a + i0b);
    acc[1] = (e1a + e1b) + (i1a + i1b);

    float mlm = g_ml[m];
    #pragma unroll
    for (int j = 0; j < 2; j++) {
        int tl = half * 64 + tt + 32 * j;
        int t  = t0 + tl;
        if (t < T_DATA) g_sconv[m * T_DATA + t] = acc[j];
        p[tl * 11 + m] = mlm * tanhf(acc[j]);   // sweep-0: zero history
    }
    __syncthreads();

    if (tid < TILE) {
        int t = t0 + tid;
        if (t < T_DATA) {
            float s = g_b0;
            #pragma unroll
            for (int m2 = 0; m2 < M_NO; m2++) s += p[tid * 11 + m2];
            g_outA[t] = s;
        }
    }
}

// -------- K3: one Jacobi sweep. 4 chains per warp: (tap-half a/b) x (t-group 0/1). --------
__global__ __launch_bounds__(640) void k3_iter(float* __restrict__ final_out,
                                               int src_sel, int dst_sel)
{
    __shared__ __align__(16) float so[TILE + TN];
    __shared__ __align__(16) float sK[M_NO * TN];
    __shared__ float p[TILE * 11];

    const float* src = src_sel ? g_outB : g_outA;
    float* dst = (dst_sel == 2) ? final_out : (dst_sel ? g_outB : g_outA);

    int t0  = blockIdx.x * TILE;
    int tid = threadIdx.x;

    for (int i = tid; i < M_NO * TN; i += 640) sK[i] = g_K[i];
    for (int i = tid; i < TILE + TN; i += 640) {
        int t = t0 - TN + i;
        so[i] = (t >= 0 && t < T_DATA) ? src[t] : 0.f;
    }
    __syncthreads();

    int w = tid >> 5, tt = tid & 31;
    int m = w >> 1, half = w & 1;
    const float4* K4 = reinterpret_cast<const float4*>(&sK[m * TN]);
    float a0 = 0.f, a1 = 0.f, a2 = 0.f, a3 = 0.f;
    int base0 = half * 64 + tt + (TN - 1);
    #pragma unroll 2
    for (int j = 0; j < TN / 2; j += 4) {
        float4 ka = K4[j >> 2];
        float4 kb = K4[(j + 100) >> 2];
        int b  = base0 - j;
        int b2 = b - 100;
        a0 = fmaf(ka.x, so[b     ], a0); a0 = fmaf(ka.y, so[b -  1], a0);
        a0 = fmaf(ka.z, so[b -  2], a0); a0 = fmaf(ka.w, so[b -  3], a0);
        a1 = fmaf(ka.x, so[b + 32], a1); a1 = fmaf(ka.y, so[b + 31], a1);
        a1 = fmaf(ka.z, so[b + 30], a1); a1 = fmaf(ka.w, so[b + 29], a1);
        a2 = fmaf(kb.x, so[b2     ], a2); a2 = fmaf(kb.y, so[b2 -  1], a2);
        a2 = fmaf(kb.z, so[b2 -  2], a2); a2 = fmaf(kb.w, so[b2 -  3], a2);
        a3 = fmaf(kb.x, so[b2 + 32], a3); a3 = fmaf(kb.y, so[b2 + 31], a3);
        a3 = fmaf(kb.z, so[b2 + 30], a3); a3 = fmaf(kb.w, so[b2 + 29], a3);
    }
    float fb[2] = {a0 + a2, a1 + a3};

    float mlm = g_ml[m];
    #pragma unroll
    for (int j = 0; j < 2; j++) {
        int tl = half * 64 + tt + 32 * j;
        int t  = t0 + tl;
        float sc = (t < T_DATA) ? g_sconv[m * T_DATA + t] : 0.f;
        p[tl * 11 + m] = mlm * tanhf(sc + fb[j]);
    }
    __syncthreads();

    if (tid < TILE) {
        int t = t0 + tid;
        if (t < T_DATA) {
            float s = g_b0;
            #pragma unroll
            for (int m2 = 0; m2 < M_NO; m2++) s += p[tid * 11 + m2];
            dst[t] = s;
        }
    }
}

// -------- launch --------
extern "C" void kernel_launch(void* const* d_in, const int* in_sizes, int n_in,
                              void* d_out, int out_size)
{
    const float* S_e  = (const float*)d_in[0];
    const float* S_i  = (const float*)d_in[1];
    // d_in[2] = C_den (unused)
    const float* Ce   = (const float*)d_in[3];
    const float* Ci   = (const float*)d_in[4];
    const float* be   = (const float*)d_in[5];
    const float* we   = (const float*)d_in[6];
    const float* bi   = (const float*)d_in[7];
    const float* wi   = (const float*)d_in[8];
    const float* bh   = (const float*)d_in[9];
    const float* wh   = (const float*)d_in[10];
    const float* ll   = (const float*)d_in[11];
    const float* ml   = (const float*)d_in[12];
    const float* mb   = (const float*)d_in[13];
    float* out = (float*)d_out;

    int grid = (T_DATA + TILE - 1) / TILE;   // 157

    k0_small<<<1, 256>>>(be, we, bi, wi, bh, wh, ll, ml, mb);
    k1_proj<<<(2 * T_DATA * 32) / 256, 256>>>(S_e, S_i, Ce, Ci);
    k2_fused<<<grid, 640>>>();               // sconv + sweep0 -> A

    k3_iter<<<grid, 640>>>(out, 0, 1);       // A -> B   (sweep 1)
    k3_iter<<<grid, 640>>>(out, 1, 2);       // B -> out (sweep 2, final)
}

// round 7
// speedup vs baseline: 2.1084x; 1.0638x over previous
#include <cuda_runtime.h>
#include <math.h>

#define T_DATA 20000
#define E_NO   2000
#define I_NO   500
#define M_NO   10
#define TN     200
#define B_NO   12
#define TILE   160      // 125 * 160 == 20000 exactly
#define GRID   125
#define PAD_WIN 392     // TILE + TN + 32 pad (garbage-lane loads stay in-bounds)

// -------- device scratch (static, no allocation) --------
__device__ float    g_u[T_DATA];
__device__ float    g_v[T_DATA];
__device__ float    g_re[M_NO * TN];
__device__ float    g_ri[M_NO * TN];
__device__ float    g_K [M_NO * TN];
__device__ float    g_ml[M_NO];
__device__ float    g_b0;
__device__ float    g_Kl1[M_NO];        // L1 norm of K per m
__device__ unsigned g_mn_enc[M_NO];     // ordered-uint encoded min of sconv
__device__ unsigned g_mx_enc[M_NO];
__device__ int      g_act[M_NO];        // 1 = active (needs tanh+feedback), 0 = saturated
__device__ float    g_base;             // b0 + sum over saturated m of ml*sign
__device__ float    g_sconv[M_NO * T_DATA];
__device__ float    g_outA[T_DATA];
__device__ float    g_outB[T_DATA];

__device__ __forceinline__ unsigned fenc(float f) {
    unsigned u = __float_as_uint(f);
    return (u & 0x80000000u) ? ~u : (u | 0x80000000u);
}
__device__ __forceinline__ float fdec(unsigned e) {
    return (e & 0x80000000u) ? __uint_as_float(e ^ 0x80000000u) : __uint_as_float(~e);
}

// -------- K0: weight products + per-m ||K||_1 + reset classify state (1 block, 320 thr) ----
__global__ void k0_small(const float* __restrict__ be, const float* __restrict__ we,
                         const float* __restrict__ bi, const float* __restrict__ wi,
                         const float* __restrict__ bh, const float* __restrict__ wh,
                         const float* __restrict__ ll, const float* __restrict__ ml,
                         const float* __restrict__ mb)
{
    __shared__ float sKt[M_NO * TN];
    int tid = threadIdx.x;
    if (tid < M_NO) { g_mn_enc[tid] = 0xFFFFFFFFu; g_mx_enc[tid] = 0u; }
    for (int i = tid; i < M_NO * TN; i += 320) {
        int m = i / TN, k = i % TN;
        float se = 0.f, si = 0.f, sh = 0.f;
        #pragma unroll
        for (int b = 0; b < B_NO; b++) {
            se = fmaf(we[m * B_NO + b], be[b * TN + k], se);
            si = fmaf(wi[m * B_NO + b], bi[b * TN + k], si);
            sh = fmaf(wh[m * B_NO + b], bh[b * TN + k], sh);
        }
        g_re[m * TN + (TN - 1 - k)] = se;
        g_ri[m * TN + (TN - 1 - k)] = si;
        float kk = sh;
        if (k == TN - 1) kk += ll[m];          // delay d=1 carries leaf_linear
        g_K[m * TN + (TN - 1 - k)] = kk;
        sKt[m * TN + (TN - 1 - k)] = kk;
    }
    if (tid < M_NO) g_ml[tid] = ml[tid];
    if (tid == 0)   g_b0 = mb[0];
    __syncthreads();
    int w = tid >> 5, lane = tid & 31;
    if (w < M_NO) {                            // deterministic per-m L1 norm
        float s = 0.f;
        for (int j = lane; j < TN; j += 32) s += fabsf(sKt[w * TN + j]);
        #pragma unroll
        for (int o = 16; o; o >>= 1) s += __shfl_xor_sync(0xffffffffu, s, o);
        if (!lane) g_Kl1[w] = s;
    }
}

// -------- K1: u/v projections (HBM-bound, ~200 MB) --------
__global__ __launch_bounds__(256) void k1_proj(const float* __restrict__ Se,
                                               const float* __restrict__ Si,
                                               const float* __restrict__ Ce,
                                               const float* __restrict__ Ci)
{
    int gw   = (blockIdx.x * blockDim.x + threadIdx.x) >> 5;
    int lane = threadIdx.x & 31;
    if (gw < T_DATA) {
        const float4* row = reinterpret_cast<const float4*>(Se) + (size_t)gw * (E_NO / 4);
        const float4* w   = reinterpret_cast<const float4*>(Ce);
        float acc = 0.f;
        #pragma unroll 4
        for (int i = lane; i < E_NO / 4; i += 32) {
            float4 a = row[i];
            float4 b = __ldg(w + i);
            acc = fmaf(a.x, b.x, fmaf(a.y, b.y, fmaf(a.z, b.z, fmaf(a.w, b.w, acc))));
        }
        #pragma unroll
        for (int o = 16; o; o >>= 1) acc += __shfl_down_sync(0xffffffffu, acc, o);
        if (!lane) g_u[gw] = acc;
    } else {
        int t = gw - T_DATA;
        const float4* row = reinterpret_cast<const float4*>(Si) + (size_t)t * (I_NO / 4);
        const float4* w   = reinterpret_cast<const float4*>(Ci);
        float acc = 0.f;
        #pragma unroll
        for (int i = lane; i < I_NO / 4; i += 32) {
            float4 a = row[i];
            float4 b = __ldg(w + i);
            acc = fmaf(a.x, b.x, fmaf(a.y, b.y, fmaf(a.z, b.z, fmaf(a.w, b.w, acc))));
        }
        #pragma unroll
        for (int o = 16; o; o >>= 1) acc += __shfl_down_sync(0xffffffffu, acc, o);
        if (!lane) g_v[t] = acc;
    }
}

// -------- K2: sconv + min/max classify stats + fused sweep-0 --------
// 640 thr = 20 warps; warp w -> (m = w>>1, half = w&1); each warp 80 outputs:
// groups tl = half*80 + tt + {0,32,64}, third group valid only for tt<16.
__global__ __launch_bounds__(640) void k2_fused()
{
    __shared__ __align__(16) float su[PAD_WIN];
    __shared__ __align__(16) float sv[PAD_WIN];
    __shared__ __align__(16) float sre[M_NO * TN];
    __shared__ __align__(16) float sri[M_NO * TN];
    __shared__ float p[TILE * 11];

    int t0  = blockIdx.x * TILE;
    int tid = threadIdx.x;

    for (int i = tid; i < M_NO * TN; i += 640) { sre[i] = g_re[i]; sri[i] = g_ri[i]; }
    for (int i = tid; i < PAD_WIN; i += 640) {
        int t = t0 - (TN - 1) + i;
        bool ok = (t >= 0 && t < T_DATA);
        su[i] = ok ? g_u[t] : 0.f;
        sv[i] = ok ? g_v[t] : 0.f;
    }
    __syncthreads();

    int w = tid >> 5, tt = tid & 31;
    int m = w >> 1, half = w & 1;
    const float4* re4 = reinterpret_cast<const float4*>(&sre[m * TN]);
    const float4* ri4 = reinterpret_cast<const float4*>(&sri[m * TN]);
    float e0 = 0.f, e1 = 0.f, e2 = 0.f, i0 = 0.f, i1 = 0.f, i2 = 0.f;
    int base0 = half * 80 + tt + (TN - 1);
    #pragma unroll 2
    for (int d = 0; d < TN; d += 4) {
        float4 ce = re4[d >> 2];
        float4 ci = ri4[d >> 2];
        int b = base0 - d;
        e0 = fmaf(ce.x, su[b     ], e0); e0 = fmaf(ce.y, su[b -  1], e0);
        e0 = fmaf(ce.z, su[b -  2], e0); e0 = fmaf(ce.w, su[b -  3], e0);
        i0 = fmaf(ci.x, sv[b     ], i0); i0 = fmaf(ci.y, sv[b -  1], i0);
        i0 = fmaf(ci.z, sv[b -  2], i0); i0 = fmaf(ci.w, sv[b -  3], i0);
        e1 = fmaf(ce.x, su[b + 32], e1); e1 = fmaf(ce.y, su[b + 31], e1);
        e1 = fmaf(ce.z, su[b + 30], e1); e1 = fmaf(ce.w, su[b + 29], e1);
        i1 = fmaf(ci.x, sv[b + 32], i1); i1 = fmaf(ci.y, sv[b + 31], i1);
        i1 = fmaf(ci.z, sv[b + 30], i1); i1 = fmaf(ci.w, sv[b + 29], i1);
        e2 = fmaf(ce.x, su[b + 64], e2); e2 = fmaf(ce.y, su[b + 63], e2);
        e2 = fmaf(ce.z, su[b + 62], e2); e2 = fmaf(ce.w, su[b + 61], e2);
        i2 = fmaf(ci.x, sv[b + 64], i2); i2 = fmaf(ci.y, sv[b + 63], i2);
        i2 = fmaf(ci.z, sv[b + 62], i2); i2 = fmaf(ci.w, sv[b + 61], i2);
    }
    float a0 = e0 + i0, a1 = e1 + i1, a2 = e2 + i2;
    bool v2 = (tt < 16);

    // per-m min/max of sconv (classification stats); integer atomics => deterministic
    float mn = fminf(fminf(a0, a1), v2 ? a2 : a0);
    float mx = fmaxf(fmaxf(a0, a1), v2 ? a2 : a0);
    #pragma unroll
    for (int o = 16; o; o >>= 1) {
        mn = fminf(mn, __shfl_xor_sync(0xffffffffu, mn, o));
        mx = fmaxf(mx, __shfl_xor_sync(0xffffffffu, mx, o));
    }
    if (tt == 0) {
        atomicMin(&g_mn_enc[m], fenc(mn));
        atomicMax(&g_mx_enc[m], fenc(mx));
    }

    float mlm = g_ml[m];
    int tl0 = half * 80 + tt;
    g_sconv[m * T_DATA + t0 + tl0     ] = a0;  p[(tl0     ) * 11 + m] = mlm * tanhf(a0);
    g_sconv[m * T_DATA + t0 + tl0 + 32] = a1;  p[(tl0 + 32) * 11 + m] = mlm * tanhf(a1);
    if (v2) {
        g_sconv[m * T_DATA + t0 + tl0 + 64] = a2;
        p[(tl0 + 64) * 11 + m] = mlm * tanhf(a2);
    }
    __syncthreads();

    if (tid < TILE) {
        float s = g_b0;
        #pragma unroll
        for (int m2 = 0; m2 < M_NO; m2++) s += p[tid * 11 + m2];
        g_outA[t0 + tid] = s;
    }
}

// -------- K2b: classify m's (1 warp). Saturated iff provably |sconv+fb| beyond fp32 tanh=+-1.
__global__ void k2b_classify()
{
    int tid = threadIdx.x;
    float b0 = g_b0;
    float ob = fabsf(b0);                       // bound on |out|
    #pragma unroll
    for (int m = 0; m < M_NO; m++) ob += fabsf(g_ml[m]);
    __shared__ float sc[M_NO];
    if (tid < M_NO) {
        float mn = fdec(g_mn_enc[tid]);
        float mx = fdec(g_mx_enc[tid]);
        float thr = 10.0f + ob * g_Kl1[tid];    // tanhf(x)==1.0f exactly for x>9.011
        int sp = (mn >  thr);
        int sn = (mx < -thr);
        g_act[tid] = !(sp || sn);
        sc[tid] = sp ? g_ml[tid] : (sn ? -g_ml[tid] : 0.f);
    }
    __syncwarp();
    if (tid == 0) {
        float s = b0;
        #pragma unroll
        for (int m = 0; m < M_NO; m++) s += sc[m];
        g_base = s;
    }
}

// -------- K3: one Jacobi sweep; saturated m's skip all work --------
__global__ __launch_bounds__(640) void k3_iter(float* __restrict__ final_out,
                                               int src_sel, int dst_sel)
{
    __shared__ __align__(16) float so[PAD_WIN];
    __shared__ __align__(16) float sK[M_NO * TN];
    __shared__ float p[TILE * 11];

    const float* src = src_sel ? g_outB : g_outA;
    float* dst = (dst_sel == 2) ? final_out : (dst_sel ? g_outB : g_outA);

    int t0  = blockIdx.x * TILE;
    int tid = threadIdx.x;
    int w = tid >> 5, tt = tid & 31;
    int m = w >> 1, half = w & 1;
    int act = g_act[m];

    for (int i = tid; i < PAD_WIN; i += 640) {
        int t = t0 - TN + i;
        so[i] = (t >= 0 && t < T_DATA) ? src[t] : 0.f;
    }
    for (int i = tid; i < TILE * 11; i += 640) p[i] = 0.f;
    if (act) {
        int ptid = half * 32 + tt;
        for (int i = ptid; i < TN; i += 64) sK[m * TN + i] = g_K[m * TN + i];
    }
    __syncthreads();

    if (act) {
        const float4* K4 = reinterpret_cast<const float4*>(&sK[m * TN]);
        float a0 = 0.f, a1 = 0.f, a2 = 0.f;
        int base0 = half * 80 + tt + (TN - 1);
        #pragma unroll 2
        for (int j = 0; j < TN; j += 4) {
            float4 k4 = K4[j >> 2];
            int b = base0 - j;
            a0 = fmaf(k4.x, so[b     ], a0); a0 = fmaf(k4.y, so[b -  1], a0);
            a0 = fmaf(k4.z, so[b -  2], a0); a0 = fmaf(k4.w, so[b -  3], a0);
            a1 = fmaf(k4.x, so[b + 32], a1); a1 = fmaf(k4.y, so[b + 31], a1);
            a1 = fmaf(k4.z, so[b + 30], a1); a1 = fmaf(k4.w, so[b + 29], a1);
            a2 = fmaf(k4.x, so[b + 64], a2); a2 = fmaf(k4.y, so[b + 63], a2);
            a2 = fmaf(k4.z, so[b + 62], a2); a2 = fmaf(k4.w, so[b + 61], a2);
        }
        float mlm = g_ml[m];
        int tl0 = half * 80 + tt;
        p[(tl0     ) * 11 + m] = mlm * tanhf(g_sconv[m * T_DATA + t0 + tl0     ] + a0);
        p[(tl0 + 32) * 11 + m] = mlm * tanhf(g_sconv[m * T_DATA + t0 + tl0 + 32] + a1);
        if (tt < 16)
            p[(tl0 + 64) * 11 + m] = mlm * tanhf(g_sconv[m * T_DATA + t0 + tl0 + 64] + a2);
    }
    __syncthreads();

    if (tid < TILE) {
        float s = g_base;
        #pragma unroll
        for (int m2 = 0; m2 < M_NO; m2++) s += p[tid * 11 + m2];
        dst[t0 + tid] = s;
    }
}

// -------- launch --------
extern "C" void kernel_launch(void* const* d_in, const int* in_sizes, int n_in,
                              void* d_out, int out_size)
{
    const float* S_e  = (const float*)d_in[0];
    const float* S_i  = (const float*)d_in[1];
    // d_in[2] = C_den (unused)
    const float* Ce   = (const float*)d_in[3];
    const float* Ci   = (const float*)d_in[4];
    const float* be   = (const float*)d_in[5];
    const float* we   = (const float*)d_in[6];
    const float* bi   = (const float*)d_in[7];
    const float* wi   = (const float*)d_in[8];
    const float* bh   = (const float*)d_in[9];
    const float* wh   = (const float*)d_in[10];
    const float* ll   = (const float*)d_in[11];
    const float* ml   = (const float*)d_in[12];
    const float* mb   = (const float*)d_in[13];
    float* out = (float*)d_out;

    k0_small<<<1, 320>>>(be, we, bi, wi, bh, wh, ll, ml, mb);
    k1_proj<<<(2 * T_DATA * 32) / 256, 256>>>(S_e, S_i, Ce, Ci);
    k2_fused<<<GRID, 640>>>();               // sconv + classify stats + sweep0 -> A
    k2b_classify<<<1, 32>>>();

    k3_iter<<<GRID, 640>>>(out, 0, 1);       // A -> B   (sweep 1)
    k3_iter<<<GRID, 640>>>(out, 1, 2);       // B -> out (sweep 2, final)
}

// round 8
// speedup vs baseline: 2.2521x; 1.0682x over previous
#include <cuda_runtime.h>
#include <math.h>

#define T_DATA 20000
#define E_NO   2000
#define I_NO   500
#define M_NO   10
#define TN     200
#define B_NO   12
#define TILE   160       // 125 * 160 == 20000 exactly
#define GRID   125
#define PAD_WIN 392      // k2 window: TILE + TN + pad
#define W1      384      // k3 sweep-1 halo outputs per block
#define OW      584      // k3 out0 window: 424 left halo + 160
#define S1PAD   416      // s1 padded (garbage-lane reads stay in-bounds)

// -------- device scratch (static, no allocation) --------
__device__ float    g_u[T_DATA];
__device__ float    g_v[T_DATA];
__device__ float    g_sconv[M_NO * T_DATA];   // [m][t]
__device__ float    g_outA[T_DATA];           // sweep-0 output
// classification stats; static-init, atomics idempotent across graph replays
__device__ unsigned g_mn_enc[M_NO] = {0xFFFFFFFFu,0xFFFFFFFFu,0xFFFFFFFFu,0xFFFFFFFFu,0xFFFFFFFFu,
                                      0xFFFFFFFFu,0xFFFFFFFFu,0xFFFFFFFFu,0xFFFFFFFFu,0xFFFFFFFFu};
__device__ unsigned g_mx_enc[M_NO] = {0,0,0,0,0,0,0,0,0,0};

__device__ __forceinline__ unsigned fenc(float f) {
    unsigned u = __float_as_uint(f);
    return (u & 0x80000000u) ? ~u : (u | 0x80000000u);
}
__device__ __forceinline__ float fdec(unsigned e) {
    return (e & 0x80000000u) ? __uint_as_float(e ^ 0x80000000u) : __uint_as_float(~e);
}

// -------- K1: u[t] = S_e[t,:].Ce[0,:] ; v[t] = S_i[t,:].Ci[0,:]  (HBM-bound, ~200 MB) ----
__global__ __launch_bounds__(256) void k1_proj(const float* __restrict__ Se,
                                               const float* __restrict__ Si,
                                               const float* __restrict__ Ce,
                                               const float* __restrict__ Ci)
{
    int gw   = (blockIdx.x * blockDim.x + threadIdx.x) >> 5;
    int lane = threadIdx.x & 31;
    if (gw < T_DATA) {
        const float4* row = reinterpret_cast<const float4*>(Se) + (size_t)gw * (E_NO / 4);
        const float4* w   = reinterpret_cast<const float4*>(Ce);
        float acc = 0.f;
        #pragma unroll 4
        for (int i = lane; i < E_NO / 4; i += 32) {
            float4 a = row[i];
            float4 b = __ldg(w + i);
            acc = fmaf(a.x, b.x, fmaf(a.y, b.y, fmaf(a.z, b.z, fmaf(a.w, b.w, acc))));
        }
        #pragma unroll
        for (int o = 16; o; o >>= 1) acc += __shfl_down_sync(0xffffffffu, acc, o);
        if (!lane) g_u[gw] = acc;
    } else {
        int t = gw - T_DATA;
        const float4* row = reinterpret_cast<const float4*>(Si) + (size_t)t * (I_NO / 4);
        const float4* w   = reinterpret_cast<const float4*>(Ci);
        float acc = 0.f;
        #pragma unroll
        for (int i = lane; i < I_NO / 4; i += 32) {
            float4 a = row[i];
            float4 b = __ldg(w + i);
            acc = fmaf(a.x, b.x, fmaf(a.y, b.y, fmaf(a.z, b.z, fmaf(a.w, b.w, acc))));
        }
        #pragma unroll
        for (int o = 16; o; o >>= 1) acc += __shfl_down_sync(0xffffffffu, acc, o);
        if (!lane) g_v[t] = acc;
    }
}

// -------- K2: inline conv-weight prep + sconv + classify stats + fused sweep-0 ----------
// 640 thr = 20 warps; warp w -> (m=w>>1, half=w&1); outputs tl = half*80+tt+{0,32,64(tt<16)}.
__global__ __launch_bounds__(640) void k2_fused(const float* __restrict__ be,
                                                const float* __restrict__ we,
                                                const float* __restrict__ bi,
                                                const float* __restrict__ wi,
                                                const float* __restrict__ ml,
                                                const float* __restrict__ mb)
{
    __shared__ __align__(16) float su[PAD_WIN];
    __shared__ __align__(16) float sv[PAD_WIN];
    __shared__ __align__(16) float sre[M_NO * TN];
    __shared__ __align__(16) float sri[M_NO * TN];
    __shared__ float p[TILE * 11];
    __shared__ float sml[M_NO];
    __shared__ float sb0;

    int t0  = blockIdx.x * TILE;
    int tid = threadIdx.x;

    // inline weight products (replaces k0): re/ri in delay order
    for (int i = tid; i < M_NO * TN; i += 640) {
        int m = i / TN, k = i % TN;
        float se = 0.f, si = 0.f;
        #pragma unroll
        for (int b = 0; b < B_NO; b++) {
            se = fmaf(we[m * B_NO + b], be[b * TN + k], se);
            si = fmaf(wi[m * B_NO + b], bi[b * TN + k], si);
        }
        sre[m * TN + (TN - 1 - k)] = se;
        sri[m * TN + (TN - 1 - k)] = si;
    }
    if (tid < M_NO) sml[tid] = ml[tid];
    if (tid == 0)   sb0 = mb[0];
    for (int i = tid; i < PAD_WIN; i += 640) {
        int t = t0 - (TN - 1) + i;
        bool ok = (t >= 0 && t < T_DATA);
        su[i] = ok ? g_u[t] : 0.f;
        sv[i] = ok ? g_v[t] : 0.f;
    }
    __syncthreads();

    int w = tid >> 5, tt = tid & 31;
    int m = w >> 1, half = w & 1;
    const float4* re4 = reinterpret_cast<const float4*>(&sre[m * TN]);
    const float4* ri4 = reinterpret_cast<const float4*>(&sri[m * TN]);
    float e0 = 0.f, e1 = 0.f, e2 = 0.f, i0 = 0.f, i1 = 0.f, i2 = 0.f;
    int base0 = half * 80 + tt + (TN - 1);
    #pragma unroll 2
    for (int d = 0; d < TN; d += 4) {
        float4 ce = re4[d >> 2];
        float4 ci = ri4[d >> 2];
        int b = base0 - d;
        e0 = fmaf(ce.x, su[b     ], e0); e0 = fmaf(ce.y, su[b -  1], e0);
        e0 = fmaf(ce.z, su[b -  2], e0); e0 = fmaf(ce.w, su[b -  3], e0);
        i0 = fmaf(ci.x, sv[b     ], i0); i0 = fmaf(ci.y, sv[b -  1], i0);
        i0 = fmaf(ci.z, sv[b -  2], i0); i0 = fmaf(ci.w, sv[b -  3], i0);
        e1 = fmaf(ce.x, su[b + 32], e1); e1 = fmaf(ce.y, su[b + 31], e1);
        e1 = fmaf(ce.z, su[b + 30], e1); e1 = fmaf(ce.w, su[b + 29], e1);
        i1 = fmaf(ci.x, sv[b + 32], i1); i1 = fmaf(ci.y, sv[b + 31], i1);
        i1 = fmaf(ci.z, sv[b + 30], i1); i1 = fmaf(ci.w, sv[b + 29], i1);
        e2 = fmaf(ce.x, su[b + 64], e2); e2 = fmaf(ce.y, su[b + 63], e2);
        e2 = fmaf(ce.z, su[b + 62], e2); e2 = fmaf(ce.w, su[b + 61], e2);
        i2 = fmaf(ci.x, sv[b + 64], i2); i2 = fmaf(ci.y, sv[b + 63], i2);
        i2 = fmaf(ci.z, sv[b + 62], i2); i2 = fmaf(ci.w, sv[b + 61], i2);
    }
    float a0 = e0 + i0, a1 = e1 + i1, a2 = e2 + i2;
    bool v2 = (tt < 16);

    float mn = fminf(fminf(a0, a1), v2 ? a2 : a0);
    float mx = fmaxf(fmaxf(a0, a1), v2 ? a2 : a0);
    #pragma unroll
    for (int o = 16; o; o >>= 1) {
        mn = fminf(mn, __shfl_xor_sync(0xffffffffu, mn, o));
        mx = fmaxf(mx, __shfl_xor_sync(0xffffffffu, mx, o));
    }
    if (tt == 0) {
        atomicMin(&g_mn_enc[m], fenc(mn));
        atomicMax(&g_mx_enc[m], fenc(mx));
    }

    float mlm = sml[m];
    int tl0 = half * 80 + tt;
    g_sconv[m * T_DATA + t0 + tl0     ] = a0;  p[(tl0     ) * 11 + m] = mlm * tanhf(a0);
    g_sconv[m * T_DATA + t0 + tl0 + 32] = a1;  p[(tl0 + 32) * 11 + m] = mlm * tanhf(a1);
    if (v2) {
        g_sconv[m * T_DATA + t0 + tl0 + 64] = a2;
        p[(tl0 + 64) * 11 + m] = mlm * tanhf(a2);
    }
    __syncthreads();

    if (tid < TILE) {
        float s = sb0;
        #pragma unroll
        for (int m2 = 0; m2 < M_NO; m2++) s += p[tid * 11 + m2];
        g_outA[t0 + tid] = s;
    }
}

// -------- K3 mega: per-block classify + K prep + sweep1 (384-halo) + sweep2 + out -------
__global__ __launch_bounds__(640) void k3_mega(const float* __restrict__ bh,
                                               const float* __restrict__ wh,
                                               const float* __restrict__ ll,
                                               const float* __restrict__ ml,
                                               const float* __restrict__ mb,
                                               float* __restrict__ out)
{
    __shared__ __align__(16) float so0[OW + 8];       // out0 window [t0-424, t0+160)
    __shared__ __align__(16) float sK[M_NO * TN];
    __shared__ float p1[W1 * 11];
    __shared__ __align__(16) float s1[S1PAD];         // sweep-1 outputs [t0-224, t0+160) + pad
    __shared__ float sml[M_NO];
    __shared__ float sKl1[M_NO];
    __shared__ int   sact[M_NO];
    __shared__ float sbase;

    int t0  = blockIdx.x * TILE;
    int tid = threadIdx.x;
    int w = tid >> 5, tt = tid & 31;

    // K weights (hist kernel, delay order, ll folded into delay-1)
    for (int i = tid; i < M_NO * TN; i += 640) {
        int m = i / TN, k = i % TN;
        float sh = 0.f;
        #pragma unroll
        for (int b = 0; b < B_NO; b++)
            sh = fmaf(wh[m * B_NO + b], bh[b * TN + k], sh);
        float kk = sh;
        if (k == TN - 1) kk += ll[m];
        sK[m * TN + (TN - 1 - k)] = kk;
    }
    if (tid < M_NO) sml[tid] = ml[tid];
    for (int i = tid; i < OW; i += 640) {
        int t = t0 - 424 + i;
        so0[i] = (t >= 0 && t < T_DATA) ? g_outA[t] : 0.f;
    }
    __syncthreads();

    if (w < M_NO) {                     // per-m ||K||_1 (deterministic)
        float s = 0.f;
        for (int j = tt; j < TN; j += 32) s += fabsf(sK[w * TN + j]);
        #pragma unroll
        for (int o = 16; o; o >>= 1) s += __shfl_xor_sync(0xffffffffu, s, o);
        if (!tt) sKl1[w] = s;
    }
    __syncthreads();
    if (tid == 0) {                     // classification (exact bound; tanhf(x)==1 for x>9.011)
        float b0 = mb[0];
        float ob = fabsf(b0);
        #pragma unroll
        for (int m = 0; m < M_NO; m++) ob += fabsf(sml[m]);
        float base = b0;
        #pragma unroll
        for (int m = 0; m < M_NO; m++) {
            float mn = fdec(g_mn_enc[m]);
            float mx = fdec(g_mx_enc[m]);
            float thr = 10.0f + ob * sKl1[m];
            int sp = (mn >  thr), sn = (mx < -thr);
            sact[m] = !(sp || sn);
            base += sp ? sml[m] : (sn ? -sml[m] : 0.f);
        }
        sbase = base;
    }
    for (int i = tid; i < W1 * 11; i += 640) p1[i] = 0.f;
    __syncthreads();

    int m = w >> 1, half = w & 1;
    float mlm = sml[m];

    // ---- sweep 1 over 384-point halo: 6 t-groups per warp ----
    if (sact[m]) {
        const float4* K4 = reinterpret_cast<const float4*>(&sK[m * TN]);
        float a[6] = {0.f, 0.f, 0.f, 0.f, 0.f, 0.f};
        int base0 = half * 192 + tt + (TN - 1);   // so0 idx for out0[t-1-j], t = t0-224+tl
        #pragma unroll 2
        for (int j = 0; j < TN; j += 4) {
            float4 k4 = K4[j >> 2];
            int b = base0 - j;
            #pragma unroll
            for (int g = 0; g < 6; g++) {
                int bg = b + 32 * g;
                a[g] = fmaf(k4.x, so0[bg    ], a[g]);
                a[g] = fmaf(k4.y, so0[bg - 1], a[g]);
                a[g] = fmaf(k4.z, so0[bg - 2], a[g]);
                a[g] = fmaf(k4.w, so0[bg - 3], a[g]);
            }
        }
        #pragma unroll
        for (int g = 0; g < 6; g++) {
            int tl = half * 192 + tt + 32 * g;
            int t  = t0 - 224 + tl;
            float sc = (t >= 0) ? g_sconv[m * T_DATA + t] : 0.f;
            p1[tl * 11 + m] = mlm * tanhf(sc + a[g]);
        }
    }
    __syncthreads();

    // reduce to s1 (s1=0 for t<0 and in pad region)
    if (tid < S1PAD) {
        float s = 0.f;
        if (tid < W1) {
            int t = t0 - 224 + tid;
            if (t >= 0) {
                s = sbase;
                #pragma unroll
                for (int m2 = 0; m2 < M_NO; m2++) s += p1[tid * 11 + m2];
            }
        }
        s1[tid] = s;
    }
    __syncthreads();
    for (int i = tid; i < TILE * 11; i += 640) p1[i] = 0.f;
    __syncthreads();

    // ---- sweep 2 over the 160 real outputs ----
    if (sact[m]) {
        const float4* K4 = reinterpret_cast<const float4*>(&sK[m * TN]);
        float c0 = 0.f, c1 = 0.f, c2 = 0.f;
        int b0i = half * 80 + tt + 223;           // s1 idx for s1[t-1-j], t = t0+tl2
        #pragma unroll 2
        for (int j = 0; j < TN; j += 4) {
            float4 k4 = K4[j >> 2];
            int b = b0i - j;
            c0 = fmaf(k4.x, s1[b     ], c0); c0 = fmaf(k4.y, s1[b -  1], c0);
            c0 = fmaf(k4.z, s1[b -  2], c0); c0 = fmaf(k4.w, s1[b -  3], c0);
            c1 = fmaf(k4.x, s1[b + 32], c1); c1 = fmaf(k4.y, s1[b + 31], c1);
            c1 = fmaf(k4.z, s1[b + 30], c1); c1 = fmaf(k4.w, s1[b + 29], c1);
            c2 = fmaf(k4.x, s1[b + 64], c2); c2 = fmaf(k4.y, s1[b + 63], c2);
            c2 = fmaf(k4.z, s1[b + 62], c2); c2 = fmaf(k4.w, s1[b + 61], c2);
        }
        int tl = half * 80 + tt;
        p1[(tl     ) * 11 + m] = mlm * tanhf(g_sconv[m * T_DATA + t0 + tl     ] + c0);
        p1[(tl + 32) * 11 + m] = mlm * tanhf(g_sconv[m * T_DATA + t0 + tl + 32] + c1);
        if (tt < 16)
            p1[(tl + 64) * 11 + m] = mlm * tanhf(g_sconv[m * T_DATA + t0 + tl + 64] + c2);
    }
    __syncthreads();

    if (tid < TILE) {
        float s = sbase;
        #pragma unroll
        for (int m2 = 0; m2 < M_NO; m2++) s += p1[tid * 11 + m2];
        out[t0 + tid] = s;
    }
}

// -------- launch: 3 kernels --------
extern "C" void kernel_launch(void* const* d_in, const int* in_sizes, int n_in,
                              void* d_out, int out_size)
{
    const float* S_e  = (const float*)d_in[0];
    const float* S_i  = (const float*)d_in[1];
    // d_in[2] = C_den (unused)
    const float* Ce   = (const float*)d_in[3];
    const float* Ci   = (const float*)d_in[4];
    const float* be   = (const float*)d_in[5];
    const float* we   = (const float*)d_in[6];
    const float* bi   = (const float*)d_in[7];
    const float* wi   = (const float*)d_in[8];
    const float* bh   = (const float*)d_in[9];
    const float* wh   = (const float*)d_in[10];
    const float* ll   = (const float*)d_in[11];
    const float* ml   = (const float*)d_in[12];
    const float* mb   = (const float*)d_in[13];
    float* out = (float*)d_out;

    k1_proj<<<(2 * T_DATA * 32) / 256, 256>>>(S_e, S_i, Ce, Ci);
    k2_fused<<<GRID, 640>>>(be, we, bi, wi, ml, mb);
    k3_mega<<<GRID, 640>>>(bh, wh, ll, ml, mb, out);
}